// round 13
// baseline (speedup 1.0000x reference)
#include <cuda_runtime.h>
#include <cuda_fp16.h>

typedef unsigned long long u64;
typedef unsigned int u32;

#define B_  32
#define C_  64
#define CP  (C_ / 2)
#define T_  20000
#define K1  100
#define K2  50
#define T1  19901
#define T1P 19904             /* padded row stride in halves */
#define T2  19852

/* ---- Kernel A (fp16 m16n8k16 MMA) config ---- */
#define THA 128               /* 4 warps; each warp: 1024 outputs */
#define TA_BLK 4096
#define NTILE_A 5
#define XWIN 4208             /* halves: 3*1024 + 64*15 + 176 */
#define NH2 (XWIN / 2)        /* 2104 half2 */
#define XS_H2 2368            /* swizzled (j + 4*(j>>5)) + pad; also ys staging */

/* ---- Kernel C config (round-10 shape: sa2 + group sums) ---- */
#define THC 256
#define RC  8
#define TC  (THC * RC)        /* 2048 */
#define NTILE_C 10
#define NAC (TC + K2 - 1)     /* 2097 */
#define NGRP 263              /* ceil(NAC/8) */

/* device scratch */
__device__ __half g_yh[(size_t)B_ * C_ * T1P];     /* ~81 MB, planar per channel */
__device__ float g_ps[C_ * B_ * NTILE_A];
__device__ float g_pq[C_ * B_ * NTILE_A];
__device__ float g_scale[C_];
__device__ float g_shift[C_];

__device__ __forceinline__ u32 h2u(__half2 h) {
    return *reinterpret_cast<u32*>(&h);
}

/* m16n8k16 fp16 MMA, fp32 accum.
   A: a0=(g,2cl..+1) a1=(g+8,2cl..+1) a2=(g,2cl+8..+9) a3=(g+8,2cl+8..+9)
   B: b0=(k=2cl..+1, n=g) b1=(k=2cl+8..+9, n=g)
   D: c0=(g,2cl) c1=(g,2cl+1) c2=(g+8,2cl) c3=(g+8,2cl+1) */
#define MMA16(D, a0, a1, a2, a3, b0, b1) \
    asm("mma.sync.aligned.m16n8k16.row.col.f32.f16.f16.f32 " \
        "{%0,%1,%2,%3}, {%4,%5,%6,%7}, {%8,%9}, {%0,%1,%2,%3};" \
        : "+f"(D[0]), "+f"(D[1]), "+f"(D[2]), "+f"(D[3]) \
        : "r"(a0), "r"(a1), "r"(a2), "r"(a3), "r"(b0), "r"(b1))

/* stride-8 access swizzle (kernel C): step 9 (coprime 32) */
__device__ __forceinline__ int swz8(int i) { return i + (i >> 3); }

/* =====================================================================
 * Kernel A: depthwise bandpass conv as fp16 k16 Toeplitz GEMM.
 * Warp tile: out[tbw + 64m + n + 8d], m<16, n<8, d<8 (1024 outputs).
 * D_d[m][n] = sum_k A[m][k] * w[k - n - 8d]; 11 k16-steps, 60 MMAs.
 * B fragments shared across deltas: j = 2ks - d, j in [-1, 13].
 * ===================================================================== */
__global__ void __launch_bounds__(THA)
conv_band_mma(const float* __restrict__ x, const float* __restrict__ w_band)
{
    __shared__ __half2 xh[XS_H2];
    __shared__ float   ws[K1];
    __shared__ float   rsum[4], rsq[4];
    __half2* ys = xh;   /* staging alias, used post-sync */

    const int tile = blockIdx.x;
    const int c    = blockIdx.y;
    const int b    = blockIdx.z;
    const int tid  = threadIdx.x;
    const int t0   = tile * TA_BLK;

    const float* __restrict__ xp = x + ((size_t)(b * C_ + c)) * T_;
    if (tid < K1) ws[tid] = w_band[c * K1 + tid];

    /* fill x window as half2, swizzle j -> j + 4*(j>>5) */
    for (int j = tid; j < NH2; j += THA) {
        const int gt = t0 + 2 * j;
        float v0 = (gt     < T_) ? xp[gt]     : 0.f;
        float v1 = (gt + 1 < T_) ? xp[gt + 1] : 0.f;
        xh[j + 4 * (j >> 5)] = __floats2half2_rn(v0, v1);
    }
    __syncthreads();

    const int wrp  = tid >> 5;
    const int lane = tid & 31;
    const int g    = lane >> 2;
    const int cl   = lane & 3;

    /* B fragments: jj = j+1, j in [-1,13].
       b0 = {w[8j+2cl-g], w[8j+2cl+1-g]}, b1 = {w[8j+2cl+8-g], w[8j+2cl+9-g]} */
    u32 bbl[15], bbh[15];
#pragma unroll
    for (int jj = 0; jj < 15; ++jj) {
        const int p = 8 * (jj - 1) + 2 * cl - g;
        float f0 = (p     >= 0 && p     < K1) ? ws[p]     : 0.f;
        float f1 = (p + 1 >= 0 && p + 1 < K1) ? ws[p + 1] : 0.f;
        float f2 = (p + 8 >= 0 && p + 8 < K1) ? ws[p + 8] : 0.f;
        float f3 = (p + 9 >= 0 && p + 9 < K1) ? ws[p + 9] : 0.f;
        bbl[jj] = h2u(__floats2half2_rn(f0, f1));
        bbh[jj] = h2u(__floats2half2_rn(f2, f3));
    }

    /* A pointer (u32 = half2 units): swz(32*(16wrp+g)) + cl = 36*(16wrp+g) + cl */
    const u32* pxu = reinterpret_cast<const u32*>(xh) + 36 * (16 * wrp + g) + cl;

    float D[8][4];
#pragma unroll
    for (int d = 0; d < 8; ++d)
#pragma unroll
        for (int e = 0; e < 4; ++e) D[d][e] = 0.f;

#pragma unroll
    for (int ks = 0; ks < 11; ++ks) {
        const int ofs = 8 * ks + 4 * (ks >> 2);
        const u32 a0 = pxu[ofs];
        const u32 a2 = pxu[ofs + 4];
        const u32 a1 = pxu[ofs + 288];
        const u32 a3 = pxu[ofs + 292];
#pragma unroll
        for (int d = 0; d < 8; ++d) {
            const int j = 2 * ks - d;
            if (j >= -1 && j <= 13)
                MMA16(D[d], a0, a1, a2, a3, bbl[j + 1], bbh[j + 1]);
        }
    }

    /* stats from fp32 accumulators; interior fast path */
    const int tbw = t0 + 1024 * wrp;
    float s = 0.f, q = 0.f;
    if (t0 + TA_BLK <= T1) {
#pragma unroll
        for (int d = 0; d < 8; ++d) {
#pragma unroll
            for (int e = 0; e < 4; ++e) {
                const float v = D[d][e];
                s += v;
                q = fmaf(v, v, q);
            }
        }
    } else {
#pragma unroll
        for (int d = 0; d < 8; ++d) {
            const int l0 = 64 * g + 8 * d + 2 * cl;
            const int l1 = l0 + 512;
            const float v0 = D[d][0], v1 = D[d][1], v2 = D[d][2], v3 = D[d][3];
            if (tbw + l0     < T1) { s += v0; q = fmaf(v0, v0, q); }
            if (tbw + l0 + 1 < T1) { s += v1; q = fmaf(v1, v1, q); }
            if (tbw + l1     < T1) { s += v2; q = fmaf(v2, v2, q); }
            if (tbw + l1 + 1 < T1) { s += v3; q = fmaf(v3, v3, q); }
        }
    }

    /* mainloop reads of xh complete -> safe to alias as ys */
    __syncthreads();

#pragma unroll
    for (int d = 0; d < 8; ++d) {
        const int yb = 576 * wrp + 36 * g + cl;
        ys[yb + 4 * d]       = __floats2half2_rn(D[d][0], D[d][1]);
        ys[yb + 4 * d + 288] = __floats2half2_rn(D[d][2], D[d][3]);
    }

#pragma unroll
    for (int o = 16; o; o >>= 1) {
        s += __shfl_down_sync(0xffffffffu, s, o);
        q += __shfl_down_sync(0xffffffffu, q, o);
    }
    if (lane == 0) { rsum[wrp] = s; rsq[wrp] = q; }
    __syncthreads();

    __half* __restrict__ yg = g_yh + ((size_t)(b * C_ + c)) * T1P + t0;
#pragma unroll
    for (int jj = 0; jj < 4; ++jj) {
        const int r  = tid + 128 * jj;
        const int i2 = 4 * r;
        const int sw = i2 + 4 * (i2 >> 5);
        const int h0 = 8 * r;
        if (t0 + h0 + 7 < T1) {
            *reinterpret_cast<uint4*>(yg + h0) =
                *reinterpret_cast<const uint4*>(ys + sw);
        } else {
            const __half* yh = reinterpret_cast<const __half*>(ys + sw);
#pragma unroll
            for (int e = 0; e < 8; ++e)
                if (t0 + h0 + e < T1) yg[h0 + e] = yh[e];
        }
    }

    if (tid == 0) {
        const int pidx = (c * B_ + b) * NTILE_A + tile;
        g_ps[pidx] = rsum[0] + rsum[1] + rsum[2] + rsum[3];
        g_pq[pidx] = rsq[0] + rsq[1] + rsq[2] + rsq[3];
    }
}

/* =====================================================================
 * Kernel B: per-channel stats -> scale/shift
 * ===================================================================== */
__global__ void __launch_bounds__(256)
stats_kernel(const float* __restrict__ gamma, const float* __restrict__ beta)
{
    const int c   = blockIdx.x;
    const int tid = threadIdx.x;
    const int NP  = B_ * NTILE_A;

    float s = 0.f, q = 0.f;
    for (int i = tid; i < NP; i += 256) {
        s += g_ps[c * NP + i];
        q += g_pq[c * NP + i];
    }
#pragma unroll
    for (int o = 16; o; o >>= 1) {
        s += __shfl_down_sync(0xffffffffu, s, o);
        q += __shfl_down_sync(0xffffffffu, q, o);
    }
    __shared__ float rs[8], rq[8];
    const int w = tid >> 5, l = tid & 31;
    if (l == 0) { rs[w] = s; rq[w] = q; }
    __syncthreads();
    if (tid == 0) {
        float S = 0.f, Q = 0.f;
#pragma unroll
        for (int i = 0; i < 8; ++i) { S += rs[i]; Q += rq[i]; }
        const float n    = (float)B_ * (float)T1;
        const float mean = S / n;
        const float var  = Q / n - mean * mean;
        const float sc   = gamma[c] * rsqrtf(var + 1e-5f);
        g_scale[c] = sc;
        g_shift[c] = beta[c] - mean * sc;
    }
}

/* =====================================================================
 * Kernel C: round-10 version (best measured): affine + abs + box
 * lowpass, group sums computed during fill -> 8-load warm-up.
 * ===================================================================== */
__global__ void __launch_bounds__(THC)
lowpass_kernel(const float* __restrict__ w_low, const float* __restrict__ b_low,
               float* __restrict__ out)
{
    __shared__ float2 sa2[NAC + (NAC >> 3) + 2];
    __shared__ float2 grp2[NGRP + 1];

    const int tile = blockIdx.x;
    const int cc   = blockIdx.y;
    const int b    = blockIdx.z;
    const int tid  = threadIdx.x;
    const int t0   = tile * TC;

    const float2 sc = make_float2(g_scale[2 * cc], g_scale[2 * cc + 1]);
    const float2 sh = make_float2(g_shift[2 * cc], g_shift[2 * cc + 1]);
    const __half* __restrict__ yp0 = g_yh + ((size_t)(b * C_ + 2 * cc)) * T1P;
    const __half* __restrict__ yp1 = yp0 + T1P;

    for (int j = tid; j < NGRP; j += THC) {
        const int i0 = 8 * j;
        const int gt = t0 + i0;
        float2 gs = make_float2(0.f, 0.f);
        if (gt + 7 < T1 && i0 + 7 < NAC) {
            uint4 u0 = *reinterpret_cast<const uint4*>(yp0 + gt);
            uint4 u1 = *reinterpret_cast<const uint4*>(yp1 + gt);
            const __half2* h0 = reinterpret_cast<const __half2*>(&u0);
            const __half2* h1 = reinterpret_cast<const __half2*>(&u1);
#pragma unroll
            for (int p = 0; p < 4; ++p) {
                float2 v0 = __half22float2(h0[p]);
                float2 v1 = __half22float2(h1[p]);
                float2 va = make_float2(fabsf(fmaf(v0.x, sc.x, sh.x)),
                                        fabsf(fmaf(v1.x, sc.y, sh.y)));
                float2 vb = make_float2(fabsf(fmaf(v0.y, sc.x, sh.x)),
                                        fabsf(fmaf(v1.y, sc.y, sh.y)));
                sa2[swz8(i0 + 2 * p)]     = va;
                sa2[swz8(i0 + 2 * p + 1)] = vb;
                gs.x += va.x + vb.x;
                gs.y += va.y + vb.y;
            }
        } else {
#pragma unroll
            for (int e = 0; e < 8; ++e) {
                if (i0 + e < NAC) {
                    float a0 = (gt + e < T1) ? __half2float(yp0[gt + e]) : 0.f;
                    float a1 = (gt + e < T1) ? __half2float(yp1[gt + e]) : 0.f;
                    float2 v = make_float2(fabsf(fmaf(a0, sc.x, sh.x)),
                                           fabsf(fmaf(a1, sc.y, sh.y)));
                    sa2[swz8(i0 + e)] = v;
                    gs.x += v.x;
                    gs.y += v.y;
                }
            }
        }
        grp2[j] = gs;
    }
    __syncthreads();

    const int base = tid * RC;
    const float wl0 = w_low[(2 * cc) * K2];
    const float wl1 = w_low[(2 * cc + 1) * K2];
    const float bl0 = b_low[2 * cc];
    const float bl1 = b_low[2 * cc + 1];

    float2 s;
    {
        float2 g0 = grp2[tid],     g1 = grp2[tid + 1];
        float2 g2 = grp2[tid + 2], g3 = grp2[tid + 3];
        float2 g4 = grp2[tid + 4], g5 = grp2[tid + 5];
        float2 e0 = sa2[swz8(base + 48)];
        float2 e1 = sa2[swz8(base + 49)];
        s.x = ((g0.x + g1.x) + (g2.x + g3.x)) + ((g4.x + g5.x) + (e0.x + e1.x));
        s.y = ((g0.y + g1.y) + (g2.y + g3.y)) + ((g4.y + g5.y) + (e0.y + e1.y));
    }

    float2 z[RC];
    z[0] = s;
#pragma unroll
    for (int r = 1; r < RC; ++r) {
        float2 a = sa2[swz8(base + r + K2 - 1)];
        float2 d = sa2[swz8(base + r - 1)];
        s.x += a.x - d.x;
        s.y += a.y - d.y;
        z[r] = s;
    }

    float* __restrict__ o0 = out + ((size_t)(b * C_ + 2 * cc)) * T2 + t0 + base;
    float* __restrict__ o1 = o0 + T2;

    if (t0 + TC <= T2) {
        float4* __restrict__ o0v = reinterpret_cast<float4*>(o0);
        float4* __restrict__ o1v = reinterpret_cast<float4*>(o1);
#pragma unroll
        for (int g2i = 0; g2i < RC / 4; ++g2i) {
            o0v[g2i] = make_float4(fmaf(z[4 * g2i].x, wl0, bl0), fmaf(z[4 * g2i + 1].x, wl0, bl0),
                                   fmaf(z[4 * g2i + 2].x, wl0, bl0), fmaf(z[4 * g2i + 3].x, wl0, bl0));
            o1v[g2i] = make_float4(fmaf(z[4 * g2i].y, wl1, bl1), fmaf(z[4 * g2i + 1].y, wl1, bl1),
                                   fmaf(z[4 * g2i + 2].y, wl1, bl1), fmaf(z[4 * g2i + 3].y, wl1, bl1));
        }
    } else {
#pragma unroll
        for (int r = 0; r < RC; ++r) {
            if (t0 + base + r < T2) {
                o0[r] = fmaf(z[r].x, wl0, bl0);
                o1[r] = fmaf(z[r].y, wl1, bl1);
            }
        }
    }
}

/* ===================================================================== */
extern "C" void kernel_launch(void* const* d_in, const int* in_sizes, int n_in,
                              void* d_out, int out_size)
{
    const float* x      = (const float*)d_in[0];
    const float* w_band = (const float*)d_in[1];
    const float* gamma  = (const float*)d_in[2];
    const float* beta   = (const float*)d_in[3];
    const float* w_low  = (const float*)d_in[4];
    const float* b_low  = (const float*)d_in[5];
    float* out = (float*)d_out;

    dim3 ga(NTILE_A, C_, B_);
    conv_band_mma<<<ga, THA>>>(x, w_band);

    stats_kernel<<<C_, 256>>>(gamma, beta);

    dim3 gc(NTILE_C, CP, B_);
    lowpass_kernel<<<gc, THC>>>(w_low, b_low, out);
}

// round 14
// speedup vs baseline: 1.3988x; 1.3988x over previous
#include <cuda_runtime.h>
#include <cuda_fp16.h>

typedef unsigned long long u64;
typedef unsigned int u32;

#define B_  32
#define C_  64
#define CP  (C_ / 2)
#define T_  20000
#define K1  100
#define K2  50
#define T1  19901
#define T1P 19904             /* padded row stride in halves */
#define T2  19852

/* ---- Kernel A (tf32 k8 MMA) config ---- */
#define THA 128
#define TA_BLK 4096
#define NTILE_A 5
#define XWIN 4200
#define XS_WORDS 4464

/* ---- Kernel C config (round-10: sa2 + group sums) ---- */
#define THC 256
#define RC  8
#define TC  (THC * RC)        /* 2048 */
#define NTILE_C 10
#define NAC (TC + K2 - 1)     /* 2097 */
#define NGRP 263

/* device scratch */
__device__ __half g_yh[(size_t)B_ * C_ * T1P];
__device__ float g_ps[C_ * B_ * NTILE_A];
__device__ float g_pq[C_ * B_ * NTILE_A];
__device__ float g_scale[C_];
__device__ float g_shift[C_];

__device__ __forceinline__ u32 f2tf32(float f) {
    u32 r;
    asm("cvt.rna.tf32.f32 %0, %1;" : "=r"(r) : "f"(f));
    return r;
}

#define MMA8(D, a0, a1, a2, a3, b0, b1) \
    asm("mma.sync.aligned.m16n8k8.row.col.f32.tf32.tf32.f32 " \
        "{%0,%1,%2,%3}, {%4,%5,%6,%7}, {%8,%9}, {%0,%1,%2,%3};" \
        : "+f"(D[0]), "+f"(D[1]), "+f"(D[2]), "+f"(D[3]) \
        : "r"(a0), "r"(a1), "r"(a2), "r"(a3), "r"(b0), "r"(b1))

/* stride-8 access swizzle: step 9 (coprime 32) */
__device__ __forceinline__ int swz8(int i) { return i + (i >> 3); }

/* =====================================================================
 * Kernel A: round-9 tf32 k8 Toeplitz GEMM, fill via cp.async
 * (raw fp32 bits fed as tf32: HW reads high mantissa bits; boundary
 * tile uses src-size zero-fill form).
 * ===================================================================== */
__global__ void __launch_bounds__(THA, 8)
conv_band_mma(const float* __restrict__ x, const float* __restrict__ w_band)
{
    __shared__ u32   xs[XS_WORDS];
    __shared__ float ws[K1];
    __shared__ float rsum[4], rsq[4];
    __half2* ys = reinterpret_cast<__half2*>(xs);

    const int tile = blockIdx.x;
    const int c    = blockIdx.y;
    const int b    = blockIdx.z;
    const int tid  = threadIdx.x;
    const int t0   = tile * TA_BLK;

    const float* __restrict__ xp = x + ((size_t)(b * C_ + c)) * T_;
    if (tid < K1) ws[tid] = w_band[c * K1 + tid];

    /* fill x window via cp.async, 16B chunks; swizzle i -> i + 4*(i>>6)
       keeps 4-word groups contiguous (64 mult of 4). */
    {
        const u32 sbase = (u32)__cvta_generic_to_shared(xs);
        if (t0 + XWIN <= T_) {
            for (int j = tid; j < XWIN / 4; j += THA) {
                const int i = 4 * j;
                const u32 dst = sbase + 4u * (u32)(i + 4 * (i >> 6));
                const float* src = xp + t0 + i;
                asm volatile("cp.async.ca.shared.global [%0], [%1], 16;"
                             :: "r"(dst), "l"(src) : "memory");
            }
        } else {
            for (int j = tid; j < XWIN / 4; j += THA) {
                const int i = 4 * j;
                const u32 dst = sbase + 4u * (u32)(i + 4 * (i >> 6));
                const int gt = t0 + i;
                int nb = (T_ - gt) * 4;
                nb = nb < 0 ? 0 : (nb > 16 ? 16 : nb);
                const float* src = xp + (gt < T_ ? gt : 0);
                asm volatile("cp.async.ca.shared.global [%0], [%1], 16, %2;"
                             :: "r"(dst), "l"(src), "r"(nb) : "memory");
            }
        }
        asm volatile("cp.async.commit_group;" ::: "memory");
        asm volatile("cp.async.wait_group 0;" ::: "memory");
    }
    __syncthreads();

    const int wrp  = tid >> 5;
    const int lane = tid & 31;
    const int g    = lane >> 2;
    const int cl   = lane & 3;

    u32 bb0[14], bb1[14];
#pragma unroll
    for (int j = 0; j < 14; ++j) {
        const int i0 = 8 * j + cl - g;
        const int i1 = i0 + 4;
        bb0[j] = (i0 >= 0 && i0 < K1) ? f2tf32(ws[i0]) : 0u;
        bb1[j] = (i1 >= 0 && i1 < K1) ? f2tf32(ws[i1]) : 0u;
    }

    const u32* px = xs + 1088 * wrp + 68 * g + cl;

    float D[8][4];
#pragma unroll
    for (int d = 0; d < 8; ++d)
#pragma unroll
        for (int e = 0; e < 4; ++e) D[d][e] = 0.f;

#pragma unroll
    for (int ks8 = 0; ks8 < 21; ++ks8) {
        const int ofs = 8 * ks8 + 4 * (ks8 >> 3);
        const u32 a0 = px[ofs];
        const u32 a2 = px[ofs + 4];
        const u32 a1 = px[ofs + 544];
        const u32 a3 = px[ofs + 548];
#pragma unroll
        for (int d = 0; d < 8; ++d) {
            const int j = ks8 - d;
            if (j >= 0 && j < 14)
                MMA8(D[d], a0, a1, a2, a3, bb0[j], bb1[j]);
        }
    }

    const int tbw = t0 + 1024 * wrp;
    float s = 0.f, q = 0.f;
    if (t0 + TA_BLK <= T1) {
#pragma unroll
        for (int d = 0; d < 8; ++d) {
#pragma unroll
            for (int e = 0; e < 4; ++e) {
                const float v = D[d][e];
                s += v;
                q = fmaf(v, v, q);
            }
        }
    } else {
#pragma unroll
        for (int d = 0; d < 8; ++d) {
            const int l0 = 64 * g + 8 * d + 2 * cl;
            const int l1 = l0 + 512;
            const float v0 = D[d][0], v1 = D[d][1], v2 = D[d][2], v3 = D[d][3];
            if (tbw + l0     < T1) { s += v0; q = fmaf(v0, v0, q); }
            if (tbw + l0 + 1 < T1) { s += v1; q = fmaf(v1, v1, q); }
            if (tbw + l1     < T1) { s += v2; q = fmaf(v2, v2, q); }
            if (tbw + l1 + 1 < T1) { s += v3; q = fmaf(v3, v3, q); }
        }
    }

    __syncthreads();

#pragma unroll
    for (int d = 0; d < 8; ++d) {
        const int yb = 576 * wrp + 36 * g + cl;
        ys[yb + 4 * d]       = __floats2half2_rn(D[d][0], D[d][1]);
        ys[yb + 4 * d + 288] = __floats2half2_rn(D[d][2], D[d][3]);
    }

#pragma unroll
    for (int o = 16; o; o >>= 1) {
        s += __shfl_down_sync(0xffffffffu, s, o);
        q += __shfl_down_sync(0xffffffffu, q, o);
    }
    if (lane == 0) { rsum[wrp] = s; rsq[wrp] = q; }
    __syncthreads();

    __half* __restrict__ yg = g_yh + ((size_t)(b * C_ + c)) * T1P + t0;
#pragma unroll
    for (int jj = 0; jj < 4; ++jj) {
        const int r  = tid + 128 * jj;
        const int i2 = 4 * r;
        const int sw = i2 + 4 * (i2 >> 5);
        const int h0 = 8 * r;
        if (t0 + h0 + 7 < T1) {
            *reinterpret_cast<uint4*>(yg + h0) =
                *reinterpret_cast<const uint4*>(ys + sw);
        } else {
            const __half* yh = reinterpret_cast<const __half*>(ys + sw);
#pragma unroll
            for (int e = 0; e < 8; ++e)
                if (t0 + h0 + e < T1) yg[h0 + e] = yh[e];
        }
    }

    if (tid == 0) {
        const int pidx = (c * B_ + b) * NTILE_A + tile;
        g_ps[pidx] = rsum[0] + rsum[1] + rsum[2] + rsum[3];
        g_pq[pidx] = rsq[0] + rsq[1] + rsq[2] + rsq[3];
    }
}

/* =====================================================================
 * Kernel B: per-channel stats -> scale/shift
 * ===================================================================== */
__global__ void __launch_bounds__(256)
stats_kernel(const float* __restrict__ gamma, const float* __restrict__ beta)
{
    const int c   = blockIdx.x;
    const int tid = threadIdx.x;
    const int NP  = B_ * NTILE_A;

    float s = 0.f, q = 0.f;
    for (int i = tid; i < NP; i += 256) {
        s += g_ps[c * NP + i];
        q += g_pq[c * NP + i];
    }
#pragma unroll
    for (int o = 16; o; o >>= 1) {
        s += __shfl_down_sync(0xffffffffu, s, o);
        q += __shfl_down_sync(0xffffffffu, q, o);
    }
    __shared__ float rs[8], rq[8];
    const int w = tid >> 5, l = tid & 31;
    if (l == 0) { rs[w] = s; rq[w] = q; }
    __syncthreads();
    if (tid == 0) {
        float S = 0.f, Q = 0.f;
#pragma unroll
        for (int i = 0; i < 8; ++i) { S += rs[i]; Q += rq[i]; }
        const float n    = (float)B_ * (float)T1;
        const float mean = S / n;
        const float var  = Q / n - mean * mean;
        const float sc   = gamma[c] * rsqrtf(var + 1e-5f);
        g_scale[c] = sc;
        g_shift[c] = beta[c] - mean * sc;
    }
}

/* =====================================================================
 * Kernel C: round-10 version (best measured).
 * ===================================================================== */
__global__ void __launch_bounds__(THC)
lowpass_kernel(const float* __restrict__ w_low, const float* __restrict__ b_low,
               float* __restrict__ out)
{
    __shared__ float2 sa2[NAC + (NAC >> 3) + 2];
    __shared__ float2 grp2[NGRP + 1];

    const int tile = blockIdx.x;
    const int cc   = blockIdx.y;
    const int b    = blockIdx.z;
    const int tid  = threadIdx.x;
    const int t0   = tile * TC;

    const float2 sc = make_float2(g_scale[2 * cc], g_scale[2 * cc + 1]);
    const float2 sh = make_float2(g_shift[2 * cc], g_shift[2 * cc + 1]);
    const __half* __restrict__ yp0 = g_yh + ((size_t)(b * C_ + 2 * cc)) * T1P;
    const __half* __restrict__ yp1 = yp0 + T1P;

    for (int j = tid; j < NGRP; j += THC) {
        const int i0 = 8 * j;
        const int gt = t0 + i0;
        float2 gs = make_float2(0.f, 0.f);
        if (gt + 7 < T1 && i0 + 7 < NAC) {
            uint4 u0 = *reinterpret_cast<const uint4*>(yp0 + gt);
            uint4 u1 = *reinterpret_cast<const uint4*>(yp1 + gt);
            const __half2* h0 = reinterpret_cast<const __half2*>(&u0);
            const __half2* h1 = reinterpret_cast<const __half2*>(&u1);
#pragma unroll
            for (int p = 0; p < 4; ++p) {
                float2 v0 = __half22float2(h0[p]);
                float2 v1 = __half22float2(h1[p]);
                float2 va = make_float2(fabsf(fmaf(v0.x, sc.x, sh.x)),
                                        fabsf(fmaf(v1.x, sc.y, sh.y)));
                float2 vb = make_float2(fabsf(fmaf(v0.y, sc.x, sh.x)),
                                        fabsf(fmaf(v1.y, sc.y, sh.y)));
                sa2[swz8(i0 + 2 * p)]     = va;
                sa2[swz8(i0 + 2 * p + 1)] = vb;
                gs.x += va.x + vb.x;
                gs.y += va.y + vb.y;
            }
        } else {
#pragma unroll
            for (int e = 0; e < 8; ++e) {
                if (i0 + e < NAC) {
                    float a0 = (gt + e < T1) ? __half2float(yp0[gt + e]) : 0.f;
                    float a1 = (gt + e < T1) ? __half2float(yp1[gt + e]) : 0.f;
                    float2 v = make_float2(fabsf(fmaf(a0, sc.x, sh.x)),
                                           fabsf(fmaf(a1, sc.y, sh.y)));
                    sa2[swz8(i0 + e)] = v;
                    gs.x += v.x;
                    gs.y += v.y;
                }
            }
        }
        grp2[j] = gs;
    }
    __syncthreads();

    const int base = tid * RC;
    const float wl0 = w_low[(2 * cc) * K2];
    const float wl1 = w_low[(2 * cc + 1) * K2];
    const float bl0 = b_low[2 * cc];
    const float bl1 = b_low[2 * cc + 1];

    float2 s;
    {
        float2 g0 = grp2[tid],     g1 = grp2[tid + 1];
        float2 g2 = grp2[tid + 2], g3 = grp2[tid + 3];
        float2 g4 = grp2[tid + 4], g5 = grp2[tid + 5];
        float2 e0 = sa2[swz8(base + 48)];
        float2 e1 = sa2[swz8(base + 49)];
        s.x = ((g0.x + g1.x) + (g2.x + g3.x)) + ((g4.x + g5.x) + (e0.x + e1.x));
        s.y = ((g0.y + g1.y) + (g2.y + g3.y)) + ((g4.y + g5.y) + (e0.y + e1.y));
    }

    float2 z[RC];
    z[0] = s;
#pragma unroll
    for (int r = 1; r < RC; ++r) {
        float2 a = sa2[swz8(base + r + K2 - 1)];
        float2 d = sa2[swz8(base + r - 1)];
        s.x += a.x - d.x;
        s.y += a.y - d.y;
        z[r] = s;
    }

    float* __restrict__ o0 = out + ((size_t)(b * C_ + 2 * cc)) * T2 + t0 + base;
    float* __restrict__ o1 = o0 + T2;

    if (t0 + TC <= T2) {
        float4* __restrict__ o0v = reinterpret_cast<float4*>(o0);
        float4* __restrict__ o1v = reinterpret_cast<float4*>(o1);
#pragma unroll
        for (int g2i = 0; g2i < RC / 4; ++g2i) {
            o0v[g2i] = make_float4(fmaf(z[4 * g2i].x, wl0, bl0), fmaf(z[4 * g2i + 1].x, wl0, bl0),
                                   fmaf(z[4 * g2i + 2].x, wl0, bl0), fmaf(z[4 * g2i + 3].x, wl0, bl0));
            o1v[g2i] = make_float4(fmaf(z[4 * g2i].y, wl1, bl1), fmaf(z[4 * g2i + 1].y, wl1, bl1),
                                   fmaf(z[4 * g2i + 2].y, wl1, bl1), fmaf(z[4 * g2i + 3].y, wl1, bl1));
        }
    } else {
#pragma unroll
        for (int r = 0; r < RC; ++r) {
            if (t0 + base + r < T2) {
                o0[r] = fmaf(z[r].x, wl0, bl0);
                o1[r] = fmaf(z[r].y, wl1, bl1);
            }
        }
    }
}

/* ===================================================================== */
extern "C" void kernel_launch(void* const* d_in, const int* in_sizes, int n_in,
                              void* d_out, int out_size)
{
    const float* x      = (const float*)d_in[0];
    const float* w_band = (const float*)d_in[1];
    const float* gamma  = (const float*)d_in[2];
    const float* beta   = (const float*)d_in[3];
    const float* w_low  = (const float*)d_in[4];
    const float* b_low  = (const float*)d_in[5];
    float* out = (float*)d_out;

    dim3 ga(NTILE_A, C_, B_);
    conv_band_mma<<<ga, THA>>>(x, w_band);

    stats_kernel<<<C_, 256>>>(gamma, beta);

    dim3 gc(NTILE_C, CP, B_);
    lowpass_kernel<<<gc, THC>>>(w_low, b_low, out);
}